// round 6
// baseline (speedup 1.0000x reference)
#include <cuda_runtime.h>
#include <cuda_bf16.h>
#include <math.h>
#include <stdint.h>

#define TT 64
#define DIMM 2048
#define SLOTSS 256
#define KS 16
#define KPER (DIMM / KS)    // 128
#define NCHUNK (KPER / 16)  // 8
#define SPAD 40
#define NB 256

// -------- device scratch --------
__device__ float g_h[TT * DIMM];
__device__ float g_x[TT * DIMM];
__device__ float g_lv[TT * DIMM];
__device__ float g_gated[TT * DIMM];
__device__ float g_er[TT * DIMM];
__device__ float g_ad[TT * DIMM];
__device__ float g_pA[KS * TT * DIMM];
__device__ float g_pB[KS * TT * DIMM];
__device__ float g_pS[KS * TT * SLOTSS];
__device__ float g_lg[TT * SLOTSS];
__device__ float g_c[TT * SLOTSS];
__device__ unsigned g_count = 0;
__device__ unsigned g_gen = 0;
// [0] = arrival counters, [1] = slab-ready flags ; 4 reducer layers x 16 tiles
__device__ unsigned g_sync[2][4][16];

__device__ __forceinline__ float sigmoidf_(float v) { return 1.f / (1.f + expf(-v)); }

enum { M_RELU = 0, M_ID, M_LIG, M_GATE };

// -------- shared memory union --------
struct SmemG { __nv_bfloat16 As[2][64][SPAD]; __nv_bfloat16 Ws[2][128][SPAD]; };
struct SmemM { float cs[64][32]; float es[64][64]; float ds[64][64]; };
struct SmemS { float rowmax[64]; float psum[2][8]; };
union SmemU { SmemG g; SmemM m; SmemS s; };

// -------- software grid barrier (all NB blocks resident) --------
__device__ __forceinline__ void gridbar() {
    __threadfence();
    __syncthreads();
    if (threadIdx.x == 0) {
        unsigned gen = *(volatile unsigned*)&g_gen;
        unsigned prev = atomicAdd(&g_count, 1);
        if (prev == NB - 1) {
            g_count = 0;
            __threadfence();
            *(volatile unsigned*)&g_gen = gen + 1;
        } else {
            while (*(volatile unsigned*)&g_gen == gen) { __nanosleep(32); }
        }
        __threadfence();
    }
    __syncthreads();
}

__device__ __forceinline__ void spin_u32(volatile unsigned* p, unsigned target) {
    while (*p < target) { __nanosleep(64); }
}

// -------- MMA helpers --------
__device__ __forceinline__ void ldsm4(uint32_t* r, uint32_t addr) {
    asm volatile("ldmatrix.sync.aligned.m8n8.x4.shared.b16 {%0,%1,%2,%3}, [%4];"
                 : "=r"(r[0]), "=r"(r[1]), "=r"(r[2]), "=r"(r[3]) : "r"(addr));
}
__device__ __forceinline__ void mma16816(float* d, const uint32_t* a, uint32_t b0, uint32_t b1) {
    asm volatile(
        "mma.sync.aligned.m16n8k16.row.col.f32.bf16.bf16.f32 "
        "{%0,%1,%2,%3}, {%4,%5,%6,%7}, {%8,%9}, {%0,%1,%2,%3};"
        : "+f"(d[0]), "+f"(d[1]), "+f"(d[2]), "+f"(d[3])
        : "r"(a[0]), "r"(a[1]), "r"(a[2]), "r"(a[3]), "r"(b0), "r"(b1));
}

// ---------------------------------------------------------------------------
// GEMM phase with split-K flags.
// WAIT: layer whose flag gates A loads (-1 none). RED: this layer's reducer
// index (-1 none). HAZ: flag checked before partial writes (WAR on buffer
// reuse; -1 none). MODE: reducer epilogue.
// ---------------------------------------------------------------------------
template <int PREP, int ACG, int WAIT, int RED, int HAZ, int MODE>
__device__ void gemm_phase(SmemU* sm, const float* __restrict__ A,
                           const float* __restrict__ W, float* __restrict__ part,
                           int Ntot, int nblk,
                           const float* __restrict__ noise, const int* __restrict__ idx,
                           float* __restrict__ outR, const float* __restrict__ bias,
                           const float* __restrict__ vw, const float* __restrict__ vb,
                           const float* __restrict__ xbuf) {
    const int bid = blockIdx.x;
    const int tid = threadIdx.x;
    const int nb = bid % nblk;
    const int kidx = bid / nblk;
    const int n0 = nb * 128;
    const int kb = kidx * KPER;

    const int a_row = tid >> 2, a_kq = (tid & 3) * 4;
    const float* Ag;
    const float* Ng = nullptr;
    if (PREP) {
        int row = __ldg(&idx[a_row]);
        Ag = A + (size_t)row * DIMM + kb + a_kq;
        Ng = noise + (size_t)a_row * DIMM + kb + a_kq;
    } else {
        Ag = A + (size_t)a_row * DIMM + kb + a_kq;
    }
    const int w_row = tid >> 1, w_kq = (tid & 1) * 8;
    const float* Wgp = W + (size_t)(n0 + w_row) * DIMM + kb + w_kq;

    const int lane = tid & 31, wid = tid >> 5;
    const int m0w = (wid >> 2) * 32;
    const int n0w = (wid & 3) * 32;
    const int gq = lane >> 3, rq = lane & 7;
    const int aoff = (m0w + (gq & 1) * 8 + rq) * SPAD + (gq >> 1) * 8;
    const int boff = (n0w + (gq >> 1) * 8 + rq) * SPAD + (gq & 1) * 8;

    const uint32_t asbase = (uint32_t)__cvta_generic_to_shared(&sm->g.As[0][0][0]);
    const uint32_t wsbase = (uint32_t)__cvta_generic_to_shared(&sm->g.Ws[0][0][0]);
    const uint32_t ABUF = 64 * SPAD * 2, WBUF = 128 * SPAD * 2;

    float avs[3][4], wvs[3][8];

#define LOAD_W(st, c)                                                        \
    {                                                                        \
        float4 u0 = __ldg((const float4*)(Wgp + (c) * 16));                  \
        float4 u1 = __ldg((const float4*)(Wgp + (c) * 16 + 4));              \
        wvs[st][0] = u0.x; wvs[st][1] = u0.y; wvs[st][2] = u0.z;             \
        wvs[st][3] = u0.w; wvs[st][4] = u1.x; wvs[st][5] = u1.y;             \
        wvs[st][6] = u1.z; wvs[st][7] = u1.w;                                \
    }
#define LOAD_A(st, c)                                                        \
    {                                                                        \
        float4 t4 = ACG ? __ldcg((const float4*)(Ag + (c) * 16))             \
                        : __ldg((const float4*)(Ag + (c) * 16));             \
        if (PREP) {                                                          \
            float4 n4 = __ldg((const float4*)(Ng + (c) * 16));               \
            t4.x = fmaf(0.01f, n4.x, t4.x); t4.y = fmaf(0.01f, n4.y, t4.y);  \
            t4.z = fmaf(0.01f, n4.z, t4.z); t4.w = fmaf(0.01f, n4.w, t4.w);  \
        }                                                                    \
        avs[st][0] = t4.x; avs[st][1] = t4.y;                                \
        avs[st][2] = t4.z; avs[st][3] = t4.w;                                \
    }
#define CVT_STORE(st, buf)                                                   \
    {                                                                        \
        _Pragma("unroll") for (int i = 0; i < 4; i++) {                      \
            __nv_bfloat16 hi = __float2bfloat16(avs[st][i]);                 \
            float rem = avs[st][i] - __bfloat162float(hi);                   \
            sm->g.As[buf][a_row][a_kq + i] = hi;                             \
            sm->g.As[buf][a_row][a_kq + i + 16] = __float2bfloat16(rem);     \
        }                                                                    \
        _Pragma("unroll") for (int i = 0; i < 8; i++) {                      \
            __nv_bfloat16 hi = __float2bfloat16(wvs[st][i]);                 \
            float rem = wvs[st][i] - __bfloat162float(hi);                   \
            sm->g.Ws[buf][w_row][w_kq + i] = hi;                             \
            sm->g.Ws[buf][w_row][w_kq + i + 16] = __float2bfloat16(rem);     \
        }                                                                    \
    }

    // prologue: W loads first (independent of flags), then wait, then A
    LOAD_W(0, 0);
    LOAD_W(1, 1);
    LOAD_W(2, 2);
    if (WAIT >= 0) {
        if (tid == 0) spin_u32(&g_sync[1][WAIT][kidx], 1u);
        __syncthreads();
        __threadfence();
    }
    LOAD_A(0, 0);
    LOAD_A(1, 1);
    LOAD_A(2, 2);
    CVT_STORE(0, 0);
    __syncthreads();

    float d[2][4][4];
#pragma unroll
    for (int mt = 0; mt < 2; mt++)
#pragma unroll
        for (int nf = 0; nf < 4; nf++)
#pragma unroll
            for (int j = 0; j < 4; j++) d[mt][nf][j] = 0.f;

#pragma unroll
    for (int c = 0; c < NCHUNK; c++) {
        const int cur = c & 1;
        if (c + 3 < NCHUNK) { LOAD_A(c % 3, c + 3); LOAD_W(c % 3, c + 3); }

        uint32_t a[2][2][4], b[2][2][4];
#pragma unroll
        for (int mt = 0; mt < 2; mt++)
#pragma unroll
            for (int sec = 0; sec < 2; sec++)
                ldsm4(a[mt][sec], asbase + cur * ABUF + (uint32_t)(aoff + mt * 16 * SPAD + sec * 16) * 2);
#pragma unroll
        for (int pr = 0; pr < 2; pr++)
#pragma unroll
            for (int sec = 0; sec < 2; sec++)
                ldsm4(b[pr][sec], wsbase + cur * WBUF + (uint32_t)(boff + pr * 16 * SPAD + sec * 16) * 2);
#pragma unroll
        for (int q = 0; q < 3; q++) {
            const int as = (q == 2) ? 1 : 0;
            const int ws = (q == 1) ? 1 : 0;
#pragma unroll
            for (int mt = 0; mt < 2; mt++)
#pragma unroll
                for (int nf = 0; nf < 4; nf++) {
                    const int pr = nf >> 1, hl = nf & 1;
                    mma16816(d[mt][nf], a[mt][as], b[pr][ws][hl * 2], b[pr][ws][hl * 2 + 1]);
                }
        }
        if (c + 1 < NCHUNK) CVT_STORE((c + 1) % 3, cur ^ 1);
        __syncthreads();
    }
#undef LOAD_W
#undef LOAD_A
#undef CVT_STORE

    // WAR guard: previous user of this partial buffer must be done reading
    if (HAZ >= 0) {
        if (tid == 0) spin_u32(&g_sync[1][HAZ][nb], 1u);
        __syncthreads();
    }

    const int mbase = kidx * 64;
#pragma unroll
    for (int mt = 0; mt < 2; mt++)
#pragma unroll
        for (int nf = 0; nf < 4; nf++) {
            const int m = m0w + mt * 16 + (lane >> 2);
            const int n = n0 + n0w + nf * 8 + (lane & 3) * 2;
            *(float2*)&part[(size_t)(mbase + m) * Ntot + n] = make_float2(d[mt][nf][0], d[mt][nf][1]);
            *(float2*)&part[(size_t)(mbase + m + 8) * Ntot + n] = make_float2(d[mt][nf][2], d[mt][nf][3]);
        }

    if (RED >= 0) {
        __threadfence();
        __syncthreads();
        if (tid == 0) atomicAdd(&g_sync[0][RED][nb], 1u);
        if (kidx == nb) {
            // designated reducer: reduce tile nb, epilogue, set flag
            if (tid == 0) spin_u32(&g_sync[0][RED][nb], (unsigned)KS);
            __syncthreads();
            __threadfence();
            const int gcol = nb * 128 + lane * 4;
            float acc[8][4];
#pragma unroll
            for (int r = 0; r < 8; r++)
#pragma unroll
                for (int j = 0; j < 4; j++) acc[r][j] = 0.f;
#pragma unroll
            for (int k = 0; k < KS; k++) {
#pragma unroll
                for (int r = 0; r < 8; r++) {
                    const int row = wid * 8 + r;
                    float4 p = __ldcg((const float4*)&part[(size_t)k * TT * DIMM + (size_t)row * DIMM + gcol]);
                    acc[r][0] += p.x; acc[r][1] += p.y; acc[r][2] += p.z; acc[r][3] += p.w;
                }
            }
            float4 b4 = __ldg((const float4*)&bias[gcol]);
            const float bb[4] = {b4.x, b4.y, b4.z, b4.w};
            float4 vw4, vb4;
            if (MODE == M_LIG) { vw4 = __ldg((const float4*)&vw[gcol]); vb4 = __ldg((const float4*)&vb[gcol]); }
            const float* vwp = (const float*)&vw4;
            const float* vbp = (const float*)&vb4;
#pragma unroll
            for (int r = 0; r < 8; r++) {
                const int row = wid * 8 + r;
                float res[4];
                float4 xv;
                if (MODE == M_GATE) xv = __ldcg((const float4*)&xbuf[(size_t)row * DIMM + gcol]);
                const float* xp = (const float*)&xv;
#pragma unroll
                for (int j = 0; j < 4; j++) {
                    const float v = acc[r][j] + bb[j];
                    if (MODE == M_RELU) {
                        res[j] = v > 0.f ? v : 0.f;
                    } else if (MODE == M_ID) {
                        res[j] = v;
                    } else if (MODE == M_LIG) {
                        float ang = fmodf(0.37699111843077515f * (float)(row + 1), 6.2831853071795865f);
                        float ps = -cosf(ang);
                        float volt = sigmoidf_(fmaf(ps, vwp[j], vbp[j]));
                        res[j] = sigmoidf_(v) * volt;
                    } else {  // M_GATE
                        res[j] = xp[j] * sigmoidf_(v);
                    }
                }
                *(float4*)&outR[(size_t)row * DIMM + gcol] = make_float4(res[0], res[1], res[2], res[3]);
            }
            __threadfence();
            __syncthreads();
            if (tid == 0) *(volatile unsigned*)&g_sync[1][RED][nb] = 1u;
        }
    }
}

// -------- fused tail reduce (R4): er+ad (lo 32768), lg (next 4096) ----------
__device__ void tail_phase(const float* __restrict__ pA, const float* __restrict__ be,
                           const float* __restrict__ pB, const float* __restrict__ bad,
                           const float* __restrict__ pS, const float* __restrict__ ba,
                           float* __restrict__ er, float* __restrict__ ad,
                           float* __restrict__ lg) {
    const int gid = blockIdx.x * 256 + threadIdx.x;
    if (gid < 32768) {
        const int flat = gid * 4;
        const int n = flat % DIMM;
        float aA[4] = {0, 0, 0, 0}, aB[4] = {0, 0, 0, 0};
#pragma unroll
        for (int k = 0; k < KS; k++) {
            float4 p = __ldcg((const float4*)&pA[(size_t)k * TT * DIMM + flat]);
            aA[0] += p.x; aA[1] += p.y; aA[2] += p.z; aA[3] += p.w;
            float4 q = __ldcg((const float4*)&pB[(size_t)k * TT * DIMM + flat]);
            aB[0] += q.x; aB[1] += q.y; aB[2] += q.z; aB[3] += q.w;
        }
        float4 e4 = __ldg((const float4*)&be[n]);
        float4 d4 = __ldg((const float4*)&bad[n]);
        const float* ep = (const float*)&e4;
        const float* dp = (const float*)&d4;
        float ro[4], ao[4];
#pragma unroll
        for (int j = 0; j < 4; j++) {
            ro[j] = sigmoidf_(aA[j] + ep[j]);
            ao[j] = aB[j] + dp[j];
        }
        *(float4*)&er[flat] = make_float4(ro[0], ro[1], ro[2], ro[3]);
        *(float4*)&ad[flat] = make_float4(ao[0], ao[1], ao[2], ao[3]);
    } else if (gid < 32768 + 4096) {
        const int flat = (gid - 32768) * 4;
        const int ns = flat % SLOTSS;
        float aS[4] = {0, 0, 0, 0};
#pragma unroll
        for (int k = 0; k < KS; k++) {
            float4 p = __ldcg((const float4*)&pS[(size_t)k * TT * SLOTSS + flat]);
            aS[0] += p.x; aS[1] += p.y; aS[2] += p.z; aS[3] += p.w;
        }
        float4 b4 = __ldg((const float4*)&ba[ns]);
        *(float4*)&lg[flat] = make_float4(aS[0] + b4.x, aS[1] + b4.y, aS[2] + b4.z, aS[3] + b4.w);
    }
}

// -------- softmax chain (R4: block 0, 256 threads) ---------------------------
__device__ void softmax_phase(SmemU* sm, const float* __restrict__ lg,
                              float* __restrict__ cbuf) {
    const int s = threadIdx.x, lane = s & 31, wid = s >> 5;
    __syncthreads();
#pragma unroll
    for (int r = 0; r < 8; r++) {
        const int row = wid * 8 + r;
        float m = -1e30f;
#pragma unroll
        for (int j = 0; j < 8; j++) m = fmaxf(m, __ldcg(&lg[row * SLOTSS + j * 32 + lane]));
#pragma unroll
        for (int o = 16; o > 0; o >>= 1) m = fmaxf(m, __shfl_xor_sync(0xffffffffu, m, o));
        if (lane == 0) sm->s.rowmax[row] = m;
    }
    __syncthreads();

    float usage = 0.f;
    for (int t = 0; t < TT; t++) {
        const float v = __ldcg(&lg[t * SLOTSS + s]) - 0.1f * usage - sm->s.rowmax[t];
        const float e = expf(v);
        float su = e;
#pragma unroll
        for (int o = 16; o > 0; o >>= 1) su += __shfl_xor_sync(0xffffffffu, su, o);
        if (lane == 0) sm->s.psum[t & 1][wid] = su;
        __syncthreads();
        float tot = 0.f;
#pragma unroll
        for (int i = 0; i < 8; i++) tot += sm->s.psum[t & 1][i];
        const float wgt = e / tot;
        cbuf[t * SLOTSS + s] = 0.5f * wgt;
        usage += wgt;
    }
}

// -------- memupd (R4: tile 32 slots x 64 dims per block) ---------------------
__device__ void memupd_phase(SmemU* sm, const float* __restrict__ cbuf,
                             const float* __restrict__ er, const float* __restrict__ ad,
                             const float* __restrict__ mem0, float* __restrict__ out) {
    const int tid = threadIdx.x;
    const int S0 = (blockIdx.x & 7) * 32;
    const int D0 = (blockIdx.x >> 3) * 64;
#pragma unroll
    for (int j = 0; j < 2; j++) {
        int f = tid + j * 256;
        int t = f >> 3, q = (f & 7) * 4;
        *(float4*)&sm->m.cs[t][q] = __ldcg((const float4*)&cbuf[(size_t)t * SLOTSS + S0 + q]);
    }
#pragma unroll
    for (int j = 0; j < 4; j++) {
        int f = tid + j * 256;
        int t = f >> 4, q = (f & 15) * 4;
        *(float4*)&sm->m.es[t][q] = __ldcg((const float4*)&er[(size_t)t * DIMM + D0 + q]);
        *(float4*)&sm->m.ds[t][q] = __ldcg((const float4*)&ad[(size_t)t * DIMM + D0 + q]);
    }
    __syncthreads();
    const int sg = (tid >> 4) * 2, dg = (tid & 15) * 4;
    float m[2][4];
#pragma unroll
    for (int j = 0; j < 2; j++)
        *(float4*)m[j] = __ldg((const float4*)&mem0[(size_t)(S0 + sg + j) * DIMM + D0 + dg]);
    for (int t = 0; t < 64; t++) {
        float c0 = sm->m.cs[t][sg], c1 = sm->m.cs[t][sg + 1];
        float4 e4 = *(const float4*)&sm->m.es[t][dg];
        float4 a4 = *(const float4*)&sm->m.ds[t][dg];
        float e[4] = {e4.x, e4.y, e4.z, e4.w};
        float a[4] = {a4.x, a4.y, a4.z, a4.w};
#pragma unroll
        for (int l = 0; l < 4; l++) {
            m[0][l] = fmaf(c0, fmaf(-e[l], m[0][l], a[l]), m[0][l]);
            m[1][l] = fmaf(c1, fmaf(-e[l], m[1][l], a[l]), m[1][l]);
        }
    }
#pragma unroll
    for (int j = 0; j < 2; j++)
        *(float4*)&out[(size_t)(S0 + sg + j) * DIMM + D0 + dg] = *(float4*)m[j];
}

// -------- mega kernel --------------------------------------------------------
__global__ __launch_bounds__(256, 2) void mega_kernel(
    const float* __restrict__ traces, const float* __restrict__ noise,
    const float* __restrict__ mem0,
    const float* __restrict__ W1, const float* __restrict__ b1,
    const float* __restrict__ W2, const float* __restrict__ b2,
    const float* __restrict__ Wl, const float* __restrict__ bl,
    const float* __restrict__ vw, const float* __restrict__ vb,
    const float* __restrict__ Wg, const float* __restrict__ bg,
    const float* __restrict__ Wa, const float* __restrict__ ba,
    const float* __restrict__ We, const float* __restrict__ be,
    const float* __restrict__ Wad, const float* __restrict__ bad,
    const int* __restrict__ idx, float* __restrict__ out) {
    __shared__ SmemU sm;

    // L1: relu(traces@W1) -> g_h            (partials pA, reducer layer 0)
    gemm_phase<1, 0, -1, 0, -1, M_RELU>(&sm, traces, W1, g_pA, DIMM, 16,
                                        noise, idx, g_h, b1, nullptr, nullptr, nullptr);
    // L2: g_h@W2 -> g_x                     (pB, layer 1)
    gemm_phase<0, 1, 0, 1, -1, M_ID>(&sm, g_h, W2, g_pB, DIMM, 16,
                                     nullptr, nullptr, g_x, b2, nullptr, nullptr, nullptr);
    // L3: lig(g_x@Wl) -> g_lv               (pA again; HAZ on layer0, layer 2)
    gemm_phase<0, 1, 1, 2, 0, M_LIG>(&sm, g_x, Wl, g_pA, DIMM, 16,
                                     nullptr, nullptr, g_lv, bl, vw, vb, nullptr);
    // L4: gate(g_lv@Wg)*x -> g_gated        (pB; HAZ layer1, layer 3)
    gemm_phase<0, 1, 2, 3, 1, M_GATE>(&sm, g_lv, Wg, g_pB, DIMM, 16,
                                      nullptr, nullptr, g_gated, bg, nullptr, nullptr, g_x);
    // trio: We (pA; HAZ layer2), Wad (pB; HAZ layer3), Wa (pS)
    gemm_phase<0, 1, 3, -1, 2, M_ID>(&sm, g_gated, We, g_pA, DIMM, 16,
                                     nullptr, nullptr, nullptr, nullptr, nullptr, nullptr, nullptr);
    __syncthreads();
    gemm_phase<0, 1, -1, -1, 3, M_ID>(&sm, g_gated, Wad, g_pB, DIMM, 16,
                                      nullptr, nullptr, nullptr, nullptr, nullptr, nullptr, nullptr);
    if (blockIdx.x < 32) {
        __syncthreads();
        gemm_phase<0, 1, -1, -1, -1, M_ID>(&sm, g_gated, Wa, g_pS, SLOTSS, 2,
                                           nullptr, nullptr, nullptr, nullptr, nullptr, nullptr, nullptr);
    }
    gridbar();

    tail_phase(g_pA, be, g_pB, bad, g_pS, ba, g_er, g_ad, g_lg);
    gridbar();

    if (blockIdx.x == 0) softmax_phase(&sm, g_lg, g_c);
    gridbar();

    memupd_phase(&sm, g_c, g_er, g_ad, mem0, out);
}

// ---------------------------------------------------------------------------
extern "C" void kernel_launch(void* const* d_in, const int* in_sizes, int n_in,
                              void* d_out, int out_size) {
    const float* traces = (const float*)d_in[0];
    const float* noise  = (const float*)d_in[1];
    const float* mem0   = (const float*)d_in[2];
    const float* W1 = (const float*)d_in[4];
    const float* b1 = (const float*)d_in[5];
    const float* W2 = (const float*)d_in[6];
    const float* b2 = (const float*)d_in[7];
    const float* Wl = (const float*)d_in[8];
    const float* bl = (const float*)d_in[9];
    const float* vw = (const float*)d_in[10];
    const float* vb = (const float*)d_in[11];
    const float* Wg = (const float*)d_in[12];
    const float* bg = (const float*)d_in[13];
    const float* Wa = (const float*)d_in[14];
    const float* ba = (const float*)d_in[15];
    const float* We = (const float*)d_in[16];
    const float* be = (const float*)d_in[17];
    const float* Wad = (const float*)d_in[18];
    const float* bad = (const float*)d_in[19];
    const int* idx = (const int*)d_in[20];
    float* out = (float*)d_out;

    // reset split-K counters/flags each call (graph-replay determinism)
    void* sync_ptr = nullptr;
    cudaGetSymbolAddress(&sync_ptr, g_sync);
    cudaMemsetAsync(sync_ptr, 0, sizeof(unsigned) * 2 * 4 * 16, 0);

    mega_kernel<<<NB, 256>>>(traces, noise, mem0, W1, b1, W2, b2, Wl, bl, vw, vb,
                             Wg, bg, Wa, ba, We, be, Wad, bad, idx, out);
}

// round 8
// speedup vs baseline: 1.5524x; 1.5524x over previous
#include <cuda_runtime.h>
#include <cuda_bf16.h>
#include <math.h>
#include <stdint.h>

#define TT 64
#define DIMM 2048
#define SLOTSS 256
#define KS 16
#define KPER (DIMM / KS)    // 128
#define NCHUNK (KPER / 16)  // 8
#define SPAD 40
#define NB 256

// -------- device scratch --------
__device__ float g_h[TT * DIMM];
__device__ float g_x[TT * DIMM];
__device__ float g_lv[TT * DIMM];
__device__ float g_gated[TT * DIMM];
__device__ float g_er[TT * DIMM];
__device__ float g_ad[TT * DIMM];
__device__ float g_pA[KS * TT * DIMM];
__device__ float g_pB[KS * TT * DIMM];
__device__ float g_pS[KS * TT * SLOTSS];
__device__ float g_lg[TT * SLOTSS];
__device__ float g_c[TT * SLOTSS];
__device__ unsigned g_count = 0;
__device__ unsigned g_gen = 0;
__device__ unsigned g_cnt[2];   // [0]=Wa partial arrivals, [1]=lg reduce arrivals

__device__ __forceinline__ float sigmoidf_(float v) { return 1.f / (1.f + expf(-v)); }

enum { M_RELU = 0, M_ID, M_LIG, M_GATE };

// -------- shared memory union --------
struct SmemG { __nv_bfloat16 As[2][64][SPAD]; __nv_bfloat16 Ws[2][128][SPAD]; };
struct SmemM { float cs[64][32]; float es[64][64]; float ds[64][64]; };
struct SmemS { float rowmax[64]; float psum[2][8]; };
union SmemU { SmemG g; SmemM m; SmemS s; };

// -------- software grid barrier (all NB blocks resident) --------
__device__ __forceinline__ void gridbar() {
    __threadfence();
    __syncthreads();
    if (threadIdx.x == 0) {
        unsigned gen = *(volatile unsigned*)&g_gen;
        unsigned prev = atomicAdd(&g_count, 1);
        if (prev == NB - 1) {
            g_count = 0;
            __threadfence();
            *(volatile unsigned*)&g_gen = gen + 1;
        } else {
            while (*(volatile unsigned*)&g_gen == gen) { __nanosleep(32); }
        }
        __threadfence();
    }
    __syncthreads();
}

__device__ __forceinline__ void spin_u32(volatile unsigned* p, unsigned target) {
    while (*p < target) { __nanosleep(64); }
}

// evict-first global load via cache-hint policy: weights are single-use,
// keep them from evicting the L2-resident partial buffers.
__device__ __forceinline__ float4 ldg_ef(const float* p) {
    float4 v;
    uint64_t pol;
    asm("createpolicy.fractional.L2::evict_first.b64 %0, 1.0;" : "=l"(pol));
    asm volatile("ld.global.nc.L2::cache_hint.v4.f32 {%0,%1,%2,%3}, [%4], %5;"
                 : "=f"(v.x), "=f"(v.y), "=f"(v.z), "=f"(v.w)
                 : "l"(p), "l"(pol));
    return v;
}

// -------- MMA helpers --------
__device__ __forceinline__ void ldsm4(uint32_t* r, uint32_t addr) {
    asm volatile("ldmatrix.sync.aligned.m8n8.x4.shared.b16 {%0,%1,%2,%3}, [%4];"
                 : "=r"(r[0]), "=r"(r[1]), "=r"(r[2]), "=r"(r[3]) : "r"(addr));
}
__device__ __forceinline__ void mma16816(float* d, const uint32_t* a, uint32_t b0, uint32_t b1) {
    asm volatile(
        "mma.sync.aligned.m16n8k16.row.col.f32.bf16.bf16.f32 "
        "{%0,%1,%2,%3}, {%4,%5,%6,%7}, {%8,%9}, {%0,%1,%2,%3};"
        : "+f"(d[0]), "+f"(d[1]), "+f"(d[2]), "+f"(d[3])
        : "r"(a[0]), "r"(a[1]), "r"(a[2]), "r"(a[3]), "r"(b0), "r"(b1));
}

// ---------------------------------------------------------------------------
// Tensor-core GEMM tile: explicit tile index (nb = tile % nblk, kidx = tile/nblk)
// ---------------------------------------------------------------------------
template <int PREP, int ACG>
__device__ void gemm_tile(SmemU* sm, const float* __restrict__ A,
                          const float* __restrict__ W, float* __restrict__ part,
                          int Ntot, int nblk, int tile,
                          const float* __restrict__ noise, const int* __restrict__ idx) {
    const int tid = threadIdx.x;
    const int nb = tile % nblk;
    const int kidx = tile / nblk;
    const int n0 = nb * 128;
    const int kb = kidx * KPER;

    const int a_row = tid >> 2, a_kq = (tid & 3) * 4;
    const float* Ag;
    const float* Ng = nullptr;
    if (PREP) {
        int row = __ldg(&idx[a_row]);
        Ag = A + (size_t)row * DIMM + kb + a_kq;
        Ng = noise + (size_t)a_row * DIMM + kb + a_kq;
    } else {
        Ag = A + (size_t)a_row * DIMM + kb + a_kq;
    }
    const int w_row = tid >> 1, w_kq = (tid & 1) * 8;
    const float* Wgp = W + (size_t)(n0 + w_row) * DIMM + kb + w_kq;

    const int lane = tid & 31, wid = tid >> 5;
    const int m0w = (wid >> 2) * 32;
    const int n0w = (wid & 3) * 32;
    const int gq = lane >> 3, rq = lane & 7;
    const int aoff = (m0w + (gq & 1) * 8 + rq) * SPAD + (gq >> 1) * 8;
    const int boff = (n0w + (gq >> 1) * 8 + rq) * SPAD + (gq & 1) * 8;

    const uint32_t asbase = (uint32_t)__cvta_generic_to_shared(&sm->g.As[0][0][0]);
    const uint32_t wsbase = (uint32_t)__cvta_generic_to_shared(&sm->g.Ws[0][0][0]);
    const uint32_t ABUF = 64 * SPAD * 2, WBUF = 128 * SPAD * 2;

    float avs[3][4], wvs[3][8];

#define LOAD_CHUNK(st, c)                                                    \
    {                                                                        \
        float4 t4 = ACG ? __ldcg((const float4*)(Ag + (c) * 16))             \
                        : ldg_ef(Ag + (c) * 16);                             \
        if (PREP) {                                                          \
            float4 n4 = ldg_ef(Ng + (c) * 16);                               \
            t4.x = fmaf(0.01f, n4.x, t4.x); t4.y = fmaf(0.01f, n4.y, t4.y);  \
            t4.z = fmaf(0.01f, n4.z, t4.z); t4.w = fmaf(0.01f, n4.w, t4.w);  \
        }                                                                    \
        avs[st][0] = t4.x; avs[st][1] = t4.y;                                \
        avs[st][2] = t4.z; avs[st][3] = t4.w;                                \
        float4 u0 = ldg_ef(Wgp + (c) * 16);                                  \
        float4 u1 = ldg_ef(Wgp + (c) * 16 + 4);                              \
        wvs[st][0] = u0.x; wvs[st][1] = u0.y; wvs[st][2] = u0.z;             \
        wvs[st][3] = u0.w; wvs[st][4] = u1.x; wvs[st][5] = u1.y;             \
        wvs[st][6] = u1.z; wvs[st][7] = u1.w;                                \
    }
#define CVT_STORE(st, buf)                                                   \
    {                                                                        \
        _Pragma("unroll") for (int i = 0; i < 4; i++) {                      \
            __nv_bfloat16 hi = __float2bfloat16(avs[st][i]);                 \
            float rem = avs[st][i] - __bfloat162float(hi);                   \
            sm->g.As[buf][a_row][a_kq + i] = hi;                             \
            sm->g.As[buf][a_row][a_kq + i + 16] = __float2bfloat16(rem);     \
        }                                                                    \
        _Pragma("unroll") for (int i = 0; i < 8; i++) {                      \
            __nv_bfloat16 hi = __float2bfloat16(wvs[st][i]);                 \
            float rem = wvs[st][i] - __bfloat162float(hi);                   \
            sm->g.Ws[buf][w_row][w_kq + i] = hi;                             \
            sm->g.Ws[buf][w_row][w_kq + i + 16] = __float2bfloat16(rem);     \
        }                                                                    \
    }

    LOAD_CHUNK(0, 0);
    LOAD_CHUNK(1, 1);
    LOAD_CHUNK(2, 2);
    CVT_STORE(0, 0);
    __syncthreads();

    float d[2][4][4];
#pragma unroll
    for (int mt = 0; mt < 2; mt++)
#pragma unroll
        for (int nf = 0; nf < 4; nf++)
#pragma unroll
            for (int j = 0; j < 4; j++) d[mt][nf][j] = 0.f;

#pragma unroll
    for (int c = 0; c < NCHUNK; c++) {
        const int cur = c & 1;
        if (c + 3 < NCHUNK) LOAD_CHUNK(c % 3, c + 3);

        uint32_t a[2][2][4], b[2][2][4];
#pragma unroll
        for (int mt = 0; mt < 2; mt++)
#pragma unroll
            for (int sec = 0; sec < 2; sec++)
                ldsm4(a[mt][sec], asbase + cur * ABUF + (uint32_t)(aoff + mt * 16 * SPAD + sec * 16) * 2);
#pragma unroll
        for (int pr = 0; pr < 2; pr++)
#pragma unroll
            for (int sec = 0; sec < 2; sec++)
                ldsm4(b[pr][sec], wsbase + cur * WBUF + (uint32_t)(boff + pr * 16 * SPAD + sec * 16) * 2);
#pragma unroll
        for (int q = 0; q < 3; q++) {
            const int as = (q == 2) ? 1 : 0;
            const int ws = (q == 1) ? 1 : 0;
#pragma unroll
            for (int mt = 0; mt < 2; mt++)
#pragma unroll
                for (int nf = 0; nf < 4; nf++) {
                    const int pr = nf >> 1, hl = nf & 1;
                    mma16816(d[mt][nf], a[mt][as], b[pr][ws][hl * 2], b[pr][ws][hl * 2 + 1]);
                }
        }
        if (c + 1 < NCHUNK) CVT_STORE((c + 1) % 3, cur ^ 1);
        __syncthreads();
    }
#undef LOAD_CHUNK
#undef CVT_STORE

    const int mbase = kidx * 64;
#pragma unroll
    for (int mt = 0; mt < 2; mt++)
#pragma unroll
        for (int nf = 0; nf < 4; nf++) {
            const int m = m0w + mt * 16 + (lane >> 2);
            const int n = n0 + n0w + nf * 8 + (lane & 3) * 2;
            *(float2*)&part[(size_t)(mbase + m) * Ntot + n] = make_float2(d[mt][nf][0], d[mt][nf][1]);
            *(float2*)&part[(size_t)(mbase + m + 8) * Ntot + n] = make_float2(d[mt][nf][2], d[mt][nf][3]);
        }
}

// -------- reduce + activation (R4 layout: 32768 threads-of-work) ------------
template <int MODE>
__device__ void reduce_phase(const float* __restrict__ part, const float* __restrict__ bias,
                             float* __restrict__ out, const float* __restrict__ xbuf,
                             const float* __restrict__ vw, const float* __restrict__ vb) {
    if (threadIdx.x >= 128) return;
    const int f4 = blockIdx.x * 128 + threadIdx.x;  // 0..32767
    const int flat = f4 * 4;
    const int t = flat / DIMM;
    const int n = flat % DIMM;
    float acc[4] = {0.f, 0.f, 0.f, 0.f};
#pragma unroll
    for (int k = 0; k < KS; k++) {
        float4 p = __ldcg((const float4*)&part[(size_t)k * TT * DIMM + flat]);
        acc[0] += p.x; acc[1] += p.y; acc[2] += p.z; acc[3] += p.w;
    }
    float4 b4 = __ldg((const float4*)&bias[n]);
    float bb[4] = {b4.x, b4.y, b4.z, b4.w};
    float res[4];
    float4 xv;
    if (MODE == M_GATE) xv = __ldcg((const float4*)&xbuf[flat]);
    const float* xp = (const float*)&xv;
#pragma unroll
    for (int j = 0; j < 4; j++) {
        const float v = acc[j] + bb[j];
        if (MODE == M_RELU) {
            res[j] = v > 0.f ? v : 0.f;
        } else if (MODE == M_ID) {
            res[j] = v;
        } else if (MODE == M_LIG) {
            float ang = fmodf(0.37699111843077515f * (float)(t + 1), 6.2831853071795865f);
            float ps = -cosf(ang);
            float volt = sigmoidf_(fmaf(ps, __ldg(&vw[n + j]), __ldg(&vb[n + j])));
            res[j] = sigmoidf_(v) * volt;
        } else {  // M_GATE
            res[j] = xp[j] * sigmoidf_(v);
        }
    }
    *(float4*)&out[flat] = make_float4(res[0], res[1], res[2], res[3]);
}

// -------- tail reduce: er + ad only (lg handled in trio) ---------------------
__device__ void tail_phase(const float* __restrict__ pA, const float* __restrict__ be,
                           const float* __restrict__ pB, const float* __restrict__ bad,
                           float* __restrict__ er, float* __restrict__ ad) {
    const int gid = blockIdx.x * 256 + threadIdx.x;
    if (gid >= 32768) return;
    const int flat = gid * 4;
    const int n = flat % DIMM;
    float aA[4] = {0, 0, 0, 0}, aB[4] = {0, 0, 0, 0};
#pragma unroll
    for (int k = 0; k < KS; k++) {
        float4 p = __ldcg((const float4*)&pA[(size_t)k * TT * DIMM + flat]);
        aA[0] += p.x; aA[1] += p.y; aA[2] += p.z; aA[3] += p.w;
        float4 q = __ldcg((const float4*)&pB[(size_t)k * TT * DIMM + flat]);
        aB[0] += q.x; aB[1] += q.y; aB[2] += q.z; aB[3] += q.w;
    }
    float4 e4 = __ldg((const float4*)&be[n]);
    float4 d4 = __ldg((const float4*)&bad[n]);
    const float* ep = (const float*)&e4;
    const float* dp = (const float*)&d4;
    float ro[4], ao[4];
#pragma unroll
    for (int j = 0; j < 4; j++) {
        ro[j] = sigmoidf_(aA[j] + ep[j]);
        ao[j] = aB[j] + dp[j];
    }
    *(float4*)&er[flat] = make_float4(ro[0], ro[1], ro[2], ro[3]);
    *(float4*)&ad[flat] = make_float4(ao[0], ao[1], ao[2], ao[3]);
}

// -------- softmax chain (R4: one block, 256 threads) --------------------------
__device__ void softmax_phase(SmemU* sm, const float* __restrict__ lg,
                              float* __restrict__ cbuf) {
    const int s = threadIdx.x, lane = s & 31, wid = s >> 5;
    __syncthreads();
#pragma unroll
    for (int r = 0; r < 8; r++) {
        const int row = wid * 8 + r;
        float m = -1e30f;
#pragma unroll
        for (int j = 0; j < 8; j++) m = fmaxf(m, __ldcg(&lg[row * SLOTSS + j * 32 + lane]));
#pragma unroll
        for (int o = 16; o > 0; o >>= 1) m = fmaxf(m, __shfl_xor_sync(0xffffffffu, m, o));
        if (lane == 0) sm->s.rowmax[row] = m;
    }
    __syncthreads();

    float usage = 0.f;
    for (int t = 0; t < TT; t++) {
        const float v = __ldcg(&lg[t * SLOTSS + s]) - 0.1f * usage - sm->s.rowmax[t];
        const float e = expf(v);
        float su = e;
#pragma unroll
        for (int o = 16; o > 0; o >>= 1) su += __shfl_xor_sync(0xffffffffu, su, o);
        if (lane == 0) sm->s.psum[t & 1][wid] = su;
        __syncthreads();
        float tot = 0.f;
#pragma unroll
        for (int i = 0; i < 8; i++) tot += sm->s.psum[t & 1][i];
        const float wgt = e / tot;
        cbuf[t * SLOTSS + s] = 0.5f * wgt;
        usage += wgt;
    }
}

// -------- memupd (R4: tile 32 slots x 64 dims per block) ----------------------
__device__ void memupd_phase(SmemU* sm, const float* __restrict__ cbuf,
                             const float* __restrict__ er, const float* __restrict__ ad,
                             const float* __restrict__ mem0, float* __restrict__ out) {
    const int tid = threadIdx.x;
    const int S0 = (blockIdx.x & 7) * 32;
    const int D0 = (blockIdx.x >> 3) * 64;
#pragma unroll
    for (int j = 0; j < 2; j++) {
        int f = tid + j * 256;
        int t = f >> 3, q = (f & 7) * 4;
        *(float4*)&sm->m.cs[t][q] = __ldcg((const float4*)&cbuf[(size_t)t * SLOTSS + S0 + q]);
    }
#pragma unroll
    for (int j = 0; j < 4; j++) {
        int f = tid + j * 256;
        int t = f >> 4, q = (f & 15) * 4;
        *(float4*)&sm->m.es[t][q] = __ldcg((const float4*)&er[(size_t)t * DIMM + D0 + q]);
        *(float4*)&sm->m.ds[t][q] = __ldcg((const float4*)&ad[(size_t)t * DIMM + D0 + q]);
    }
    __syncthreads();
    const int sg = (tid >> 4) * 2, dg = (tid & 15) * 4;
    float m[2][4];
#pragma unroll
    for (int j = 0; j < 2; j++)
        *(float4*)m[j] = __ldg((const float4*)&mem0[(size_t)(S0 + sg + j) * DIMM + D0 + dg]);
    for (int t = 0; t < 64; t++) {
        float c0 = sm->m.cs[t][sg], c1 = sm->m.cs[t][sg + 1];
        float4 e4 = *(const float4*)&sm->m.es[t][dg];
        float4 a4 = *(const float4*)&sm->m.ds[t][dg];
        float e[4] = {e4.x, e4.y, e4.z, e4.w};
        float a[4] = {a4.x, a4.y, a4.z, a4.w};
#pragma unroll
        for (int l = 0; l < 4; l++) {
            m[0][l] = fmaf(c0, fmaf(-e[l], m[0][l], a[l]), m[0][l]);
            m[1][l] = fmaf(c1, fmaf(-e[l], m[1][l], a[l]), m[1][l]);
        }
    }
#pragma unroll
    for (int j = 0; j < 2; j++)
        *(float4*)&out[(size_t)(S0 + sg + j) * DIMM + D0 + dg] = *(float4*)m[j];
}

// -------- mega kernel ----------------------------------------------------------
__global__ __launch_bounds__(256, 2) void mega_kernel(
    const float* __restrict__ traces, const float* __restrict__ noise,
    const float* __restrict__ mem0,
    const float* __restrict__ W1, const float* __restrict__ b1,
    const float* __restrict__ W2, const float* __restrict__ b2,
    const float* __restrict__ Wl, const float* __restrict__ bl,
    const float* __restrict__ vw, const float* __restrict__ vb,
    const float* __restrict__ Wg, const float* __restrict__ bg,
    const float* __restrict__ Wa, const float* __restrict__ ba,
    const float* __restrict__ We, const float* __restrict__ be,
    const float* __restrict__ Wad, const float* __restrict__ bad,
    const int* __restrict__ idx, float* __restrict__ out) {
    __shared__ SmemU sm;
    const int bid = blockIdx.x;
    const int tid = threadIdx.x;

    gemm_tile<1, 0>(&sm, traces, W1, g_pA, DIMM, 16, bid, noise, idx);
    gridbar();
    reduce_phase<M_RELU>(g_pA, b1, g_h, nullptr, nullptr, nullptr);
    gridbar();

    gemm_tile<0, 1>(&sm, g_h, W2, g_pA, DIMM, 16, bid, nullptr, nullptr);
    gridbar();
    reduce_phase<M_ID>(g_pA, b2, g_x, nullptr, nullptr, nullptr);
    gridbar();

    gemm_tile<0, 1>(&sm, g_x, Wl, g_pA, DIMM, 16, bid, nullptr, nullptr);
    gridbar();
    reduce_phase<M_LIG>(g_pA, bl, g_lv, nullptr, vw, vb);
    gridbar();

    gemm_tile<0, 1>(&sm, g_lv, Wg, g_pA, DIMM, 16, bid, nullptr, nullptr);
    gridbar();
    reduce_phase<M_GATE>(g_pA, bg, g_gated, g_x, nullptr, nullptr);
    gridbar();

    // ---- trio with overlapped softmax ----
    // 1) Wa (small GEMM) first on blocks 0..31, then cooperative lg reduce.
    if (bid < 32) {
        gemm_tile<0, 1>(&sm, g_gated, Wa, g_pS, SLOTSS, 2, bid, nullptr, nullptr);
        __threadfence();
        __syncthreads();
        if (tid == 0) {
            atomicAdd(&g_cnt[0], 1u);
            spin_u32(&g_cnt[0], 32u);
        }
        __syncthreads();
        __threadfence();
        // cooperative lg reduce: 4096 float4 over 32 blocks x 128 threads
        if (tid < 128) {
            const int flat = (bid * 128 + tid) * 4;
            const int ns = flat % SLOTSS;
            float aS[4] = {0, 0, 0, 0};
#pragma unroll
            for (int k = 0; k < KS; k++) {
                float4 p = __ldcg((const float4*)&g_pS[(size_t)k * TT * SLOTSS + flat]);
                aS[0] += p.x; aS[1] += p.y; aS[2] += p.z; aS[3] += p.w;
            }
            float4 b4 = __ldg((const float4*)&ba[ns]);
            *(float4*)&g_lg[flat] = make_float4(aS[0] + b4.x, aS[1] + b4.y, aS[2] + b4.z, aS[3] + b4.w);
        }
        __threadfence();
        __syncthreads();
        if (tid == 0) atomicAdd(&g_cnt[1], 1u);
    }

    // 2) softmax on block 0, We/Wad on blocks 1..255 (shifted tile map)
    if (bid == 0) {
        if (tid == 0) spin_u32(&g_cnt[1], 32u);
        __syncthreads();
        __threadfence();
        softmax_phase(&sm, g_lg, g_c);
    } else {
        const int tw = bid - 1;   // tiles 0..254
        gemm_tile<0, 1>(&sm, g_gated, We, g_pA, DIMM, 16, tw, nullptr, nullptr);
        if (bid == 254) {
            __syncthreads();
            gemm_tile<0, 1>(&sm, g_gated, We, g_pA, DIMM, 16, 255, nullptr, nullptr);
        }
        __syncthreads();
        gemm_tile<0, 1>(&sm, g_gated, Wad, g_pB, DIMM, 16, tw, nullptr, nullptr);
        if (bid == 255) {
            __syncthreads();
            gemm_tile<0, 1>(&sm, g_gated, Wad, g_pB, DIMM, 16, 255, nullptr, nullptr);
        }
    }
    gridbar();

    tail_phase(g_pA, be, g_pB, bad, g_er, g_ad);
    gridbar();

    memupd_phase(&sm, g_c, g_er, g_ad, mem0, out);
}

// ---------------------------------------------------------------------------
extern "C" void kernel_launch(void* const* d_in, const int* in_sizes, int n_in,
                              void* d_out, int out_size) {
    const float* traces = (const float*)d_in[0];
    const float* noise  = (const float*)d_in[1];
    const float* mem0   = (const float*)d_in[2];
    const float* W1 = (const float*)d_in[4];
    const float* b1 = (const float*)d_in[5];
    const float* W2 = (const float*)d_in[6];
    const float* b2 = (const float*)d_in[7];
    const float* Wl = (const float*)d_in[8];
    const float* bl = (const float*)d_in[9];
    const float* vw = (const float*)d_in[10];
    const float* vb = (const float*)d_in[11];
    const float* Wg = (const float*)d_in[12];
    const float* bg = (const float*)d_in[13];
    const float* Wa = (const float*)d_in[14];
    const float* ba = (const float*)d_in[15];
    const float* We = (const float*)d_in[16];
    const float* be = (const float*)d_in[17];
    const float* Wad = (const float*)d_in[18];
    const float* bad = (const float*)d_in[19];
    const int* idx = (const int*)d_in[20];
    float* out = (float*)d_out;

    // reset trio counters each call (graph-replay determinism)
    void* cnt_ptr = nullptr;
    cudaGetSymbolAddress(&cnt_ptr, g_cnt);
    cudaMemsetAsync(cnt_ptr, 0, sizeof(unsigned) * 2, 0);

    mega_kernel<<<NB, 256>>>(traces, noise, mem0, W1, b1, W2, b2, Wl, bl, vw, vb,
                             Wg, bg, Wa, ba, We, be, Wad, bad, idx, out);
}

// round 9
// speedup vs baseline: 1.5536x; 1.0008x over previous
#include <cuda_runtime.h>
#include <cuda_bf16.h>
#include <math.h>
#include <stdint.h>

#define TT 64
#define DIMM 2048
#define SLOTSS 256
#define KS 8
#define KPER (DIMM / KS)     // 256
#define NCHUNK (KPER / 16)   // 16
#define NBLK 32              // n-tiles per big GEMM (2048/64)
#define SPAD 40
#define NB 256

// -------- device scratch --------
__device__ float g_h[TT * DIMM];
__device__ float g_x[TT * DIMM];
__device__ float g_lv[TT * DIMM];
__device__ float g_gated[TT * DIMM];
__device__ float g_er[TT * DIMM];
__device__ float g_ad[TT * DIMM];
__device__ float g_pA[KS * TT * DIMM];
__device__ float g_pB[KS * TT * DIMM];
__device__ float g_pS[KS * TT * SLOTSS];
__device__ float g_lg[TT * SLOTSS];
__device__ float g_c[TT * SLOTSS];
__device__ unsigned g_count = 0;
__device__ unsigned g_gen = 0;
__device__ unsigned g_cnt[2];

__device__ __forceinline__ float sigmoidf_(float v) { return 1.f / (1.f + expf(-v)); }

enum { M_RELU = 0, M_ID, M_LIG, M_GATE };

// -------- shared memory union --------
struct SmemG { __nv_bfloat16 As[2][64][SPAD]; __nv_bfloat16 Ws[2][64][SPAD]; };
struct SmemM { float cs[64][32]; float es[64][64]; float ds[64][64]; };
struct SmemS { float rowmax[64]; float psum[2][8]; };
union SmemU { SmemG g; SmemM m; SmemS s; };

// -------- software grid barrier (all NB blocks resident) --------
__device__ __forceinline__ void gridbar() {
    __threadfence();
    __syncthreads();
    if (threadIdx.x == 0) {
        unsigned gen = *(volatile unsigned*)&g_gen;
        unsigned prev = atomicAdd(&g_count, 1);
        if (prev == NB - 1) {
            g_count = 0;
            __threadfence();
            *(volatile unsigned*)&g_gen = gen + 1;
        } else {
            while (*(volatile unsigned*)&g_gen == gen) { __nanosleep(32); }
        }
        __threadfence();
    }
    __syncthreads();
}

__device__ __forceinline__ void spin_u32(volatile unsigned* p, unsigned target) {
    while (*p < target) { __nanosleep(64); }
}

// evict-first global load via cache-hint policy (single-use weights)
__device__ __forceinline__ float4 ldg_ef(const float* p) {
    float4 v;
    uint64_t pol;
    asm("createpolicy.fractional.L2::evict_first.b64 %0, 1.0;" : "=l"(pol));
    asm volatile("ld.global.nc.L2::cache_hint.v4.f32 {%0,%1,%2,%3}, [%4], %5;"
                 : "=f"(v.x), "=f"(v.y), "=f"(v.z), "=f"(v.w)
                 : "l"(p), "l"(pol));
    return v;
}

// -------- MMA helpers --------
__device__ __forceinline__ void ldsm4(uint32_t* r, uint32_t addr) {
    asm volatile("ldmatrix.sync.aligned.m8n8.x4.shared.b16 {%0,%1,%2,%3}, [%4];"
                 : "=r"(r[0]), "=r"(r[1]), "=r"(r[2]), "=r"(r[3]) : "r"(addr));
}
__device__ __forceinline__ void mma16816(float* d, const uint32_t* a, uint32_t b0, uint32_t b1) {
    asm volatile(
        "mma.sync.aligned.m16n8k16.row.col.f32.bf16.bf16.f32 "
        "{%0,%1,%2,%3}, {%4,%5,%6,%7}, {%8,%9}, {%0,%1,%2,%3};"
        : "+f"(d[0]), "+f"(d[1]), "+f"(d[2]), "+f"(d[3])
        : "r"(a[0]), "r"(a[1]), "r"(a[2]), "r"(a[3]), "r"(b0), "r"(b1));
}

// ---------------------------------------------------------------------------
// Tensor-core GEMM tile 64(M) x 64(N), K-slab 256.
// tile -> nb = tile % nblk (n-tile), kidx = tile / nblk (k-slab).
// ---------------------------------------------------------------------------
template <int PREP, int ACG>
__device__ void gemm_tile(SmemU* sm, const float* __restrict__ A,
                          const float* __restrict__ W, float* __restrict__ part,
                          int Ntot, int nblk, int tile,
                          const float* __restrict__ noise, const int* __restrict__ idx) {
    const int tid = threadIdx.x;
    const int nb = tile % nblk;
    const int kidx = tile / nblk;
    const int n0 = nb * 64;
    const int kb = kidx * KPER;

    const int a_row = tid >> 2, a_kq = (tid & 3) * 4;
    const float* Ag;
    const float* Ng = nullptr;
    if (PREP) {
        int row = __ldg(&idx[a_row]);
        Ag = A + (size_t)row * DIMM + kb + a_kq;
        Ng = noise + (size_t)a_row * DIMM + kb + a_kq;
    } else {
        Ag = A + (size_t)a_row * DIMM + kb + a_kq;
    }
    const int w_row = tid >> 2, w_kq = (tid & 3) * 4;
    const float* Wgp = W + (size_t)(n0 + w_row) * DIMM + kb + w_kq;

    const int lane = tid & 31, wid = tid >> 5;
    const int m0w = (wid & 1) * 32;     // 0/32
    const int n0w = (wid >> 1) * 16;    // 0..48
    const int gq = lane >> 3, rq = lane & 7;
    const int aoff = (m0w + (gq & 1) * 8 + rq) * SPAD + (gq >> 1) * 8;
    const int boff = (n0w + (gq >> 1) * 8 + rq) * SPAD + (gq & 1) * 8;

    const uint32_t asbase = (uint32_t)__cvta_generic_to_shared(&sm->g.As[0][0][0]);
    const uint32_t wsbase = (uint32_t)__cvta_generic_to_shared(&sm->g.Ws[0][0][0]);
    const uint32_t ABUF = 64 * SPAD * 2, WBUF = 64 * SPAD * 2;

    float avs[3][4], wvs[3][4];

#define LOAD_CHUNK(st, c)                                                    \
    {                                                                        \
        float4 t4 = ACG ? __ldcg((const float4*)(Ag + (c) * 16))             \
                        : ldg_ef(Ag + (c) * 16);                             \
        if (PREP) {                                                          \
            float4 n4 = ldg_ef(Ng + (c) * 16);                               \
            t4.x = fmaf(0.01f, n4.x, t4.x); t4.y = fmaf(0.01f, n4.y, t4.y);  \
            t4.z = fmaf(0.01f, n4.z, t4.z); t4.w = fmaf(0.01f, n4.w, t4.w);  \
        }                                                                    \
        avs[st][0] = t4.x; avs[st][1] = t4.y;                                \
        avs[st][2] = t4.z; avs[st][3] = t4.w;                                \
        float4 u0 = ldg_ef(Wgp + (c) * 16);                                  \
        wvs[st][0] = u0.x; wvs[st][1] = u0.y;                                \
        wvs[st][2] = u0.z; wvs[st][3] = u0.w;                                \
    }
#define CVT_STORE(st, buf)                                                   \
    {                                                                        \
        _Pragma("unroll") for (int i = 0; i < 4; i++) {                      \
            __nv_bfloat16 hi = __float2bfloat16(avs[st][i]);                 \
            float rem = avs[st][i] - __bfloat162float(hi);                   \
            sm->g.As[buf][a_row][a_kq + i] = hi;                             \
            sm->g.As[buf][a_row][a_kq + i + 16] = __float2bfloat16(rem);     \
        }                                                                    \
        _Pragma("unroll") for (int i = 0; i < 4; i++) {                      \
            __nv_bfloat16 hi = __float2bfloat16(wvs[st][i]);                 \
            float rem = wvs[st][i] - __bfloat162float(hi);                   \
            sm->g.Ws[buf][w_row][w_kq + i] = hi;                             \
            sm->g.Ws[buf][w_row][w_kq + i + 16] = __float2bfloat16(rem);     \
        }                                                                    \
    }

    LOAD_CHUNK(0, 0);
    LOAD_CHUNK(1, 1);
    LOAD_CHUNK(2, 2);
    CVT_STORE(0, 0);
    __syncthreads();

    float d[2][2][4];
#pragma unroll
    for (int mt = 0; mt < 2; mt++)
#pragma unroll
        for (int nf = 0; nf < 2; nf++)
#pragma unroll
            for (int j = 0; j < 4; j++) d[mt][nf][j] = 0.f;

#pragma unroll
    for (int c = 0; c < NCHUNK; c++) {
        const int cur = c & 1;
        if (c + 3 < NCHUNK) LOAD_CHUNK(c % 3, c + 3);

        uint32_t a[2][2][4], b[2][4];
#pragma unroll
        for (int mt = 0; mt < 2; mt++)
#pragma unroll
            for (int sec = 0; sec < 2; sec++)
                ldsm4(a[mt][sec], asbase + cur * ABUF + (uint32_t)(aoff + mt * 16 * SPAD + sec * 16) * 2);
#pragma unroll
        for (int sec = 0; sec < 2; sec++)
            ldsm4(b[sec], wsbase + cur * WBUF + (uint32_t)(boff + sec * 16) * 2);
#pragma unroll
        for (int q = 0; q < 3; q++) {
            const int as = (q == 2) ? 1 : 0;
            const int ws = (q == 1) ? 1 : 0;
#pragma unroll
            for (int mt = 0; mt < 2; mt++)
#pragma unroll
                for (int nf = 0; nf < 2; nf++)
                    mma16816(d[mt][nf], a[mt][as], b[ws][nf * 2], b[ws][nf * 2 + 1]);
        }
        if (c + 1 < NCHUNK) CVT_STORE((c + 1) % 3, cur ^ 1);
        __syncthreads();
    }
#undef LOAD_CHUNK
#undef CVT_STORE

    const int mbase = kidx * 64;
#pragma unroll
    for (int mt = 0; mt < 2; mt++)
#pragma unroll
        for (int nf = 0; nf < 2; nf++) {
            const int m = m0w + mt * 16 + (lane >> 2);
            const int n = n0 + n0w + nf * 8 + (lane & 3) * 2;
            *(float2*)&part[(size_t)(mbase + m) * Ntot + n] = make_float2(d[mt][nf][0], d[mt][nf][1]);
            *(float2*)&part[(size_t)(mbase + m + 8) * Ntot + n] = make_float2(d[mt][nf][2], d[mt][nf][3]);
        }
}

// -------- reduce + activation: 32768 float4 items, KS=8 partials each --------
template <int MODE>
__device__ void reduce_phase(const float* __restrict__ part, const float* __restrict__ bias,
                             float* __restrict__ out, const float* __restrict__ xbuf,
                             const float* __restrict__ vw, const float* __restrict__ vb) {
    if (threadIdx.x >= 128) return;
    const int f4 = blockIdx.x * 128 + threadIdx.x;
    const int flat = f4 * 4;
    const int t = flat / DIMM;
    const int n = flat % DIMM;
    float acc[4] = {0.f, 0.f, 0.f, 0.f};
#pragma unroll
    for (int k = 0; k < KS; k++) {
        float4 p = __ldcg((const float4*)&part[(size_t)k * TT * DIMM + flat]);
        acc[0] += p.x; acc[1] += p.y; acc[2] += p.z; acc[3] += p.w;
    }
    float4 b4 = __ldg((const float4*)&bias[n]);
    float bb[4] = {b4.x, b4.y, b4.z, b4.w};
    float res[4];
    float4 xv;
    if (MODE == M_GATE) xv = __ldcg((const float4*)&xbuf[flat]);
    const float* xp = (const float*)&xv;
#pragma unroll
    for (int j = 0; j < 4; j++) {
        const float v = acc[j] + bb[j];
        if (MODE == M_RELU) {
            res[j] = v > 0.f ? v : 0.f;
        } else if (MODE == M_ID) {
            res[j] = v;
        } else if (MODE == M_LIG) {
            float ang = fmodf(0.37699111843077515f * (float)(t + 1), 6.2831853071795865f);
            float ps = -cosf(ang);
            float volt = sigmoidf_(fmaf(ps, __ldg(&vw[n + j]), __ldg(&vb[n + j])));
            res[j] = sigmoidf_(v) * volt;
        } else {  // M_GATE
            res[j] = xp[j] * sigmoidf_(v);
        }
    }
    *(float4*)&out[flat] = make_float4(res[0], res[1], res[2], res[3]);
}

// -------- tail reduce: er + ad ------------------------------------------------
__device__ void tail_phase(const float* __restrict__ pA, const float* __restrict__ be,
                           const float* __restrict__ pB, const float* __restrict__ bad,
                           float* __restrict__ er, float* __restrict__ ad) {
    const int gid = blockIdx.x * 256 + threadIdx.x;
    if (gid >= 32768) return;
    const int flat = gid * 4;
    const int n = flat % DIMM;
    float aA[4] = {0, 0, 0, 0}, aB[4] = {0, 0, 0, 0};
#pragma unroll
    for (int k = 0; k < KS; k++) {
        float4 p = __ldcg((const float4*)&pA[(size_t)k * TT * DIMM + flat]);
        aA[0] += p.x; aA[1] += p.y; aA[2] += p.z; aA[3] += p.w;
        float4 q = __ldcg((const float4*)&pB[(size_t)k * TT * DIMM + flat]);
        aB[0] += q.x; aB[1] += q.y; aB[2] += q.z; aB[3] += q.w;
    }
    float4 e4 = __ldg((const float4*)&be[n]);
    float4 d4 = __ldg((const float4*)&bad[n]);
    const float* ep = (const float*)&e4;
    const float* dp = (const float*)&d4;
    float ro[4], ao[4];
#pragma unroll
    for (int j = 0; j < 4; j++) {
        ro[j] = sigmoidf_(aA[j] + ep[j]);
        ao[j] = aB[j] + dp[j];
    }
    *(float4*)&er[flat] = make_float4(ro[0], ro[1], ro[2], ro[3]);
    *(float4*)&ad[flat] = make_float4(ao[0], ao[1], ao[2], ao[3]);
}

// -------- softmax chain (block 0, 256 threads) ---------------------------------
__device__ void softmax_phase(SmemU* sm, const float* __restrict__ lg,
                              float* __restrict__ cbuf) {
    const int s = threadIdx.x, lane = s & 31, wid = s >> 5;
    __syncthreads();
#pragma unroll
    for (int r = 0; r < 8; r++) {
        const int row = wid * 8 + r;
        float m = -1e30f;
#pragma unroll
        for (int j = 0; j < 8; j++) m = fmaxf(m, __ldcg(&lg[row * SLOTSS + j * 32 + lane]));
#pragma unroll
        for (int o = 16; o > 0; o >>= 1) m = fmaxf(m, __shfl_xor_sync(0xffffffffu, m, o));
        if (lane == 0) sm->s.rowmax[row] = m;
    }
    __syncthreads();

    float usage = 0.f;
    for (int t = 0; t < TT; t++) {
        const float v = __ldcg(&lg[t * SLOTSS + s]) - 0.1f * usage - sm->s.rowmax[t];
        const float e = expf(v);
        float su = e;
#pragma unroll
        for (int o = 16; o > 0; o >>= 1) su += __shfl_xor_sync(0xffffffffu, su, o);
        if (lane == 0) sm->s.psum[t & 1][wid] = su;
        __syncthreads();
        float tot = 0.f;
#pragma unroll
        for (int i = 0; i < 8; i++) tot += sm->s.psum[t & 1][i];
        const float wgt = e / tot;
        cbuf[t * SLOTSS + s] = 0.5f * wgt;
        usage += wgt;
    }
}

// -------- memupd (tile 32 slots x 64 dims per block) ----------------------------
__device__ void memupd_phase(SmemU* sm, const float* __restrict__ cbuf,
                             const float* __restrict__ er, const float* __restrict__ ad,
                             const float* __restrict__ mem0, float* __restrict__ out) {
    const int tid = threadIdx.x;
    const int S0 = (blockIdx.x & 7) * 32;
    const int D0 = (blockIdx.x >> 3) * 64;
#pragma unroll
    for (int j = 0; j < 2; j++) {
        int f = tid + j * 256;
        int t = f >> 3, q = (f & 7) * 4;
        *(float4*)&sm->m.cs[t][q] = __ldcg((const float4*)&cbuf[(size_t)t * SLOTSS + S0 + q]);
    }
#pragma unroll
    for (int j = 0; j < 4; j++) {
        int f = tid + j * 256;
        int t = f >> 4, q = (f & 15) * 4;
        *(float4*)&sm->m.es[t][q] = __ldcg((const float4*)&er[(size_t)t * DIMM + D0 + q]);
        *(float4*)&sm->m.ds[t][q] = __ldcg((const float4*)&ad[(size_t)t * DIMM + D0 + q]);
    }
    __syncthreads();
    const int sg = (tid >> 4) * 2, dg = (tid & 15) * 4;
    float m[2][4];
#pragma unroll
    for (int j = 0; j < 2; j++)
        *(float4*)m[j] = __ldg((const float4*)&mem0[(size_t)(S0 + sg + j) * DIMM + D0 + dg]);
    for (int t = 0; t < 64; t++) {
        float c0 = sm->m.cs[t][sg], c1 = sm->m.cs[t][sg + 1];
        float4 e4 = *(const float4*)&sm->m.es[t][dg];
        float4 a4 = *(const float4*)&sm->m.ds[t][dg];
        float e[4] = {e4.x, e4.y, e4.z, e4.w};
        float a[4] = {a4.x, a4.y, a4.z, a4.w};
#pragma unroll
        for (int l = 0; l < 4; l++) {
            m[0][l] = fmaf(c0, fmaf(-e[l], m[0][l], a[l]), m[0][l]);
            m[1][l] = fmaf(c1, fmaf(-e[l], m[1][l], a[l]), m[1][l]);
        }
    }
#pragma unroll
    for (int j = 0; j < 2; j++)
        *(float4*)&out[(size_t)(S0 + sg + j) * DIMM + D0 + dg] = *(float4*)m[j];
}

// -------- mega kernel ------------------------------------------------------------
__global__ __launch_bounds__(256, 2) void mega_kernel(
    const float* __restrict__ traces, const float* __restrict__ noise,
    const float* __restrict__ mem0,
    const float* __restrict__ W1, const float* __restrict__ b1,
    const float* __restrict__ W2, const float* __restrict__ b2,
    const float* __restrict__ Wl, const float* __restrict__ bl,
    const float* __restrict__ vw, const float* __restrict__ vb,
    const float* __restrict__ Wg, const float* __restrict__ bg,
    const float* __restrict__ Wa, const float* __restrict__ ba,
    const float* __restrict__ We, const float* __restrict__ be,
    const float* __restrict__ Wad, const float* __restrict__ bad,
    const int* __restrict__ idx, float* __restrict__ out) {
    __shared__ SmemU sm;
    const int bid = blockIdx.x;
    const int tid = threadIdx.x;

    gemm_tile<1, 0>(&sm, traces, W1, g_pA, DIMM, NBLK, bid, noise, idx);
    gridbar();
    reduce_phase<M_RELU>(g_pA, b1, g_h, nullptr, nullptr, nullptr);
    gridbar();

    gemm_tile<0, 1>(&sm, g_h, W2, g_pA, DIMM, NBLK, bid, nullptr, nullptr);
    gridbar();
    reduce_phase<M_ID>(g_pA, b2, g_x, nullptr, nullptr, nullptr);
    gridbar();

    gemm_tile<0, 1>(&sm, g_x, Wl, g_pA, DIMM, NBLK, bid, nullptr, nullptr);
    gridbar();
    reduce_phase<M_LIG>(g_pA, bl, g_lv, nullptr, vw, vb);
    gridbar();

    gemm_tile<0, 1>(&sm, g_lv, Wg, g_pA, DIMM, NBLK, bid, nullptr, nullptr);
    gridbar();
    reduce_phase<M_GATE>(g_pA, bg, g_gated, g_x, nullptr, nullptr);
    gridbar();

    // ---- trio with overlapped softmax ----
    // 1) Wa (small GEMM: 4 n-tiles x 8 k = 32 tiles) on blocks 0..31.
    if (bid < 32) {
        gemm_tile<0, 1>(&sm, g_gated, Wa, g_pS, SLOTSS, 4, bid, nullptr, nullptr);
        __threadfence();
        __syncthreads();
        if (tid == 0) {
            atomicAdd(&g_cnt[0], 1u);
            spin_u32(&g_cnt[0], 32u);
        }
        __syncthreads();
        __threadfence();
        if (tid < 128) {
            const int flat = (bid * 128 + tid) * 4;
            const int ns = flat % SLOTSS;
            float aS[4] = {0, 0, 0, 0};
#pragma unroll
            for (int k = 0; k < KS; k++) {
                float4 p = __ldcg((const float4*)&g_pS[(size_t)k * TT * SLOTSS + flat]);
                aS[0] += p.x; aS[1] += p.y; aS[2] += p.z; aS[3] += p.w;
            }
            float4 b4 = __ldg((const float4*)&ba[ns]);
            *(float4*)&g_lg[flat] = make_float4(aS[0] + b4.x, aS[1] + b4.y, aS[2] + b4.z, aS[3] + b4.w);
        }
        __threadfence();
        __syncthreads();
        if (tid == 0) atomicAdd(&g_cnt[1], 1u);
    }

    // 2) softmax on block 0, We/Wad (256 tiles each) on blocks 1..255
    if (bid == 0) {
        if (tid == 0) spin_u32(&g_cnt[1], 32u);
        __syncthreads();
        __threadfence();
        softmax_phase(&sm, g_lg, g_c);
    } else {
        const int tw = bid - 1;   // tiles 0..254
        gemm_tile<0, 1>(&sm, g_gated, We, g_pA, DIMM, NBLK, tw, nullptr, nullptr);
        if (bid == 254) {
            __syncthreads();
            gemm_tile<0, 1>(&sm, g_gated, We, g_pA, DIMM, NBLK, 255, nullptr, nullptr);
        }
        __syncthreads();
        gemm_tile<0, 1>(&sm, g_gated, Wad, g_pB, DIMM, NBLK, tw, nullptr, nullptr);
        if (bid == 255) {
            __syncthreads();
            gemm_tile<0, 1>(&sm, g_gated, Wad, g_pB, DIMM, NBLK, 255, nullptr, nullptr);
        }
    }
    gridbar();

    tail_phase(g_pA, be, g_pB, bad, g_er, g_ad);
    gridbar();

    memupd_phase(&sm, g_c, g_er, g_ad, mem0, out);
}

// ---------------------------------------------------------------------------
extern "C" void kernel_launch(void* const* d_in, const int* in_sizes, int n_in,
                              void* d_out, int out_size) {
    const float* traces = (const float*)d_in[0];
    const float* noise  = (const float*)d_in[1];
    const float* mem0   = (const float*)d_in[2];
    const float* W1 = (const float*)d_in[4];
    const float* b1 = (const float*)d_in[5];
    const float* W2 = (const float*)d_in[6];
    const float* b2 = (const float*)d_in[7];
    const float* Wl = (const float*)d_in[8];
    const float* bl = (const float*)d_in[9];
    const float* vw = (const float*)d_in[10];
    const float* vb = (const float*)d_in[11];
    const float* Wg = (const float*)d_in[12];
    const float* bg = (const float*)d_in[13];
    const float* Wa = (const float*)d_in[14];
    const float* ba = (const float*)d_in[15];
    const float* We = (const float*)d_in[16];
    const float* be = (const float*)d_in[17];
    const float* Wad = (const float*)d_in[18];
    const float* bad = (const float*)d_in[19];
    const int* idx = (const int*)d_in[20];
    float* out = (float*)d_out;

    void* cnt_ptr = nullptr;
    cudaGetSymbolAddress(&cnt_ptr, g_cnt);
    cudaMemsetAsync(cnt_ptr, 0, sizeof(unsigned) * 2, 0);

    mega_kernel<<<NB, 256>>>(traces, noise, mem0, W1, b1, W2, b2, Wl, bl, vw, vb,
                             Wg, bg, Wa, ba, We, be, Wad, bad, idx, out);
}